// round 9
// baseline (speedup 1.0000x reference)
#include <cuda_runtime.h>
#include <cstdint>

// ---------------- problem constants ----------------
#define BB      64          // batch
#define PP      56          // grid side
#define N_TOK   3136        // P*P
#define DIMC    256         // input channels
#define HEADS   4
#define HDIM    24
#define CH      96          // HEADS*HDIM
#define CH2     192         // feat+val
#define MCNT    16          // cluster centers
#define BH      256         // B*HEADS
#define OUTC    256
#define MTOT    (BB * N_TOK)   // 200704 rows

// ---------------- scratch (device globals; no allocation allowed) ----------------
__device__ float g_w12[CH2 * DIMC];            // [192,256] concat of f_w, v_w
__device__ float g_b12[CH2];
__device__ float g_fv[(size_t)MTOT * CH2];     // [B,N,192]   feat(0:96) | val(96:192)
__device__ float g_cn[BH * MCNT * HDIM];       // l2-normalized feat centers
__device__ float g_vc[BH * MCNT * HDIM];       // raw value centers
__device__ float g_agg[BH * MCNT * HDIM];
__device__ float g_s[(size_t)BH * N_TOK];      // top-1 sim value (post leaky)
__device__ unsigned char g_m[(size_t)BH * N_TOK]; // top-1 center index
__device__ float g_merged[(size_t)MTOT * CH];  // [B,N,96] dispatched tokens

// ---------------- K0: concat weights/biases (round-1 exact) ----------------
__global__ void k_concat(const float* __restrict__ fw, const float* __restrict__ fb,
                         const float* __restrict__ vw, const float* __restrict__ vb) {
    int i = blockIdx.x * blockDim.x + threadIdx.x;
    if (i < CH * DIMC)                 g_w12[i] = fw[i];
    else if (i < CH2 * DIMC)           g_w12[i] = vw[i - CH * DIMC];
    else if (i < CH2 * DIMC + CH)      g_b12[i - CH2 * DIMC] = fb[i - CH2 * DIMC];
    else if (i < CH2 * DIMC + CH2)     g_b12[i - CH2 * DIMC] = vb[i - CH2 * DIMC - CH];
}

// ---------------- packed f32x2 helpers (sm_100 native dual-FMA) ----------------
// fma.rn.f32x2: lanewise exact fp32 FMA on a packed pair -> 2x FFMA throughput.
__device__ __forceinline__ unsigned long long bcast2(float x) {
    unsigned long long r;
    asm("mov.b64 %0, {%1, %1};" : "=l"(r) : "r"(__float_as_uint(x)));
    return r;
}
#define FMA2(acc, a2, b2) \
    asm("fma.rn.f32x2 %0, %1, %2, %0;" : "+l"(acc) : "l"(a2), "l"(b2))

// ---------------- fp32 GEMM with packed math:  C[M,NC] = A[M,K] @ W[NC,K]^T + bias ----
// Identical structure to the round-1 PASSING gemm (BM=128, BN=64, BK=8, 128 thr,
// 8x8 per thread, same smem layout/prefetch) — only the inner product is packed.
template <int K, int NC>
__device__ __forceinline__ void gemm_body(const float* __restrict__ A,
                                          const float* __restrict__ W,
                                          const float* __restrict__ bias,
                                          float* __restrict__ C) {
    __shared__ float As[8][128];
    __shared__ float Bs[8][64];
    const int tid = threadIdx.x;
    const int m0 = blockIdx.x * 128;
    const int n0 = blockIdx.y * 64;
    const int ty = tid >> 3;          // 0..15 -> 8 rows each
    const int tx = tid & 7;           // 0..7  -> 8 cols each

    const float* Ap = A + (size_t)(m0 + tid) * K;
    const int br = tid >> 1;          // 0..63
    const int bk = (tid & 1) * 4;
    const float* Wp = W + (size_t)(n0 + br) * K + bk;

    float4 a0 = *(const float4*)(Ap);
    float4 a1 = *(const float4*)(Ap + 4);
    float4 b0 = *(const float4*)(Wp);

    // accumulators: 8 rows x 4 packed col-pairs (cols 2j, 2j+1)
    unsigned long long acc2[8][4];
    const unsigned long long zz = 0ull;   // {0.f, 0.f}
#pragma unroll
    for (int i = 0; i < 8; i++)
#pragma unroll
        for (int j = 0; j < 4; j++) acc2[i][j] = zz;

    const int KT = K / 8;
    for (int kt = 0; kt < KT; ++kt) {
        As[0][tid] = a0.x; As[1][tid] = a0.y; As[2][tid] = a0.z; As[3][tid] = a0.w;
        As[4][tid] = a1.x; As[5][tid] = a1.y; As[6][tid] = a1.z; As[7][tid] = a1.w;
        Bs[bk + 0][br] = b0.x; Bs[bk + 1][br] = b0.y; Bs[bk + 2][br] = b0.z; Bs[bk + 3][br] = b0.w;
        __syncthreads();
        if (kt + 1 < KT) {
            a0 = *(const float4*)(Ap + (kt + 1) * 8);
            a1 = *(const float4*)(Ap + (kt + 1) * 8 + 4);
            b0 = *(const float4*)(Wp + (kt + 1) * 8);
        }
#pragma unroll
        for (int k = 0; k < 8; k++) {
            float ra[8];
            *(float4*)(ra)     = *(const float4*)&As[k][ty * 8];
            *(float4*)(ra + 4) = *(const float4*)&As[k][ty * 8 + 4];
            // B fragment as packed pairs: cols (2j, 2j+1) — 32B-aligned LDS.128
            unsigned long long rb2[4];
            {
                const ulonglong2 u0 = *(const ulonglong2*)&Bs[k][tx * 8];
                const ulonglong2 u1 = *(const ulonglong2*)&Bs[k][tx * 8 + 4];
                rb2[0] = u0.x; rb2[1] = u0.y; rb2[2] = u1.x; rb2[3] = u1.y;
            }
#pragma unroll
            for (int i = 0; i < 8; i++) {
                const unsigned long long a2 = bcast2(ra[i]);
                FMA2(acc2[i][0], a2, rb2[0]);
                FMA2(acc2[i][1], a2, rb2[1]);
                FMA2(acc2[i][2], a2, rb2[2]);
                FMA2(acc2[i][3], a2, rb2[3]);
            }
        }
        __syncthreads();
    }

    float bb[8];
#pragma unroll
    for (int j = 0; j < 8; j++) bb[j] = bias[n0 + tx * 8 + j];
#pragma unroll
    for (int i = 0; i < 8; i++) {
        float* Cp = C + (size_t)(m0 + ty * 8 + i) * NC + n0 + tx * 8;
        float4 o0, o1;
        o0.x = __uint_as_float((unsigned)(acc2[i][0]))       + bb[0];
        o0.y = __uint_as_float((unsigned)(acc2[i][0] >> 32)) + bb[1];
        o0.z = __uint_as_float((unsigned)(acc2[i][1]))       + bb[2];
        o0.w = __uint_as_float((unsigned)(acc2[i][1] >> 32)) + bb[3];
        o1.x = __uint_as_float((unsigned)(acc2[i][2]))       + bb[4];
        o1.y = __uint_as_float((unsigned)(acc2[i][2] >> 32)) + bb[5];
        o1.z = __uint_as_float((unsigned)(acc2[i][3]))       + bb[6];
        o1.w = __uint_as_float((unsigned)(acc2[i][3] >> 32)) + bb[7];
        *(float4*)(Cp) = o0;
        *(float4*)(Cp + 4) = o1;
    }
}

__global__ void k_gemm_fv(const float* __restrict__ x) {
    gemm_body<DIMC, CH2>(x, g_w12, g_b12, g_fv);
}
__global__ void k_gemm_proj(const float* __restrict__ pw, const float* __restrict__ pb,
                            float* __restrict__ out) {
    gemm_body<CH, OUTC>(g_merged, pw, pb, out);
}

// ---------------- K2: 4x4 adaptive-avg pooling + center l2-norm (round-1 exact) ----
__global__ void k_pool() {
    int bh = blockIdx.x, m = blockIdx.y;
    int b = bh >> 2, e = bh & 3;
    int t = threadIdx.x;
    int c = t % 48, sub = t / 48;
    int w0 = (m >> 2) * 14, h0 = (m & 3) * 14;
    int off = (c < 24) ? (e * HDIM + c) : (CH + e * HDIM + (c - 24));
    float acc = 0.f;
    for (int ti = sub; ti < 196; ti += 4) {
        int n = (w0 + ti / 14) * PP + h0 + ti % 14;
        acc += g_fv[((size_t)b * N_TOK + n) * CH2 + off];
    }
    __shared__ float red[4][48];
    __shared__ float meanv[48];
    __shared__ float sinv;
    red[sub][c] = acc;
    __syncthreads();
    if (t < 48) meanv[t] = (red[0][t] + red[1][t] + red[2][t] + red[3][t]) * (1.f / 196.f);
    __syncthreads();
    if (t == 0) {
        float s = 0.f;
        for (int i = 0; i < 24; i++) s += meanv[i] * meanv[i];
        sinv = 1.f / fmaxf(sqrtf(s), 1e-12f);
    }
    __syncthreads();
    if (t < 24)      g_cn[(bh * MCNT + m) * HDIM + t] = meanv[t] * sinv;
    else if (t < 48) g_vc[(bh * MCNT + m) * HDIM + (t - 24)] = meanv[t];
}

// ---------------- K3a: per-token cosine-sim, leaky-relu, top-1 (round-1 exact) ----
__global__ void k_assign(const float* __restrict__ alpha_p, const float* __restrict__ beta_p) {
    int bh = blockIdx.x;
    int b = bh >> 2, e = bh & 3;
    __shared__ float cnT[24][16];   // c-major for vectorized reads
    int t = threadIdx.x;
    for (int i = t; i < 384; i += 256) {
        int m = i / 24, c = i % 24;
        cnT[c][m] = g_cn[(bh * MCNT + m) * HDIM + c];
    }
    __syncthreads();
    float alpha = alpha_p[0], beta = beta_p[0];
    for (int n = t; n < N_TOK; n += 256) {
        const float* fp = g_fv + ((size_t)b * N_TOK + n) * CH2 + e * HDIM;
        float f[24];
#pragma unroll
        for (int i = 0; i < 6; i++) *(float4*)(f + 4 * i) = *(const float4*)(fp + 4 * i);
        float ss = 0.f;
#pragma unroll
        for (int c = 0; c < 24; c++) ss += f[c] * f[c];
        float inv = 1.f / fmaxf(sqrtf(ss), 1e-12f);
        float dm[16];
#pragma unroll
        for (int m = 0; m < 16; m++) dm[m] = 0.f;
#pragma unroll
        for (int c = 0; c < 24; c++) {
            float fc = f[c];
#pragma unroll
            for (int m = 0; m < 16; m++) dm[m] += cnT[c][m] * fc;
        }
        float best = -1e30f; int bm = 0;
#pragma unroll
        for (int m = 0; m < 16; m++) {
            float v = beta + alpha * (dm[m] * inv);
            v = (v > 0.f) ? v : 0.2f * v;            // leaky_relu 0.2
            if (v > best) { best = v; bm = m; }       // first-max == jnp.argmax
        }
        g_s[(size_t)bh * N_TOK + n] = best;
        g_m[(size_t)bh * N_TOK + n] = (unsigned char)bm;
    }
}

// ---------------- K3b: per-(bh,m) masked aggregation (round-1 exact) ----------------
__global__ void k_agg() {
    int bh = blockIdx.x, m = blockIdx.y;
    int b = bh >> 2, e = bh & 3;
    int t = threadIdx.x;          // 128
    float acc[24];
#pragma unroll
    for (int c = 0; c < 24; c++) acc[c] = 0.f;
    float cnt = 0.f;
    for (int n = t; n < N_TOK; n += 128) {
        if (g_m[(size_t)bh * N_TOK + n] == (unsigned char)m) {
            float s = g_s[(size_t)bh * N_TOK + n];
            const float* vp = g_fv + ((size_t)b * N_TOK + n) * CH2 + CH + e * HDIM;
            float vv[24];
#pragma unroll
            for (int i = 0; i < 6; i++) *(float4*)(vv + 4 * i) = *(const float4*)(vp + 4 * i);
#pragma unroll
            for (int c = 0; c < 24; c++) acc[c] += s * vv[c];
            cnt += 1.f;
        }
    }
    __shared__ float wsum[4][24];
    __shared__ float wcnt[4];
    int lane = t & 31, wp = t >> 5;
#pragma unroll
    for (int c = 0; c < 24; c++) {
        float v = acc[c];
        for (int o = 16; o; o >>= 1) v += __shfl_down_sync(0xffffffffu, v, o);
        if (lane == 0) wsum[wp][c] = v;
    }
    {
        float v = cnt;
        for (int o = 16; o; o >>= 1) v += __shfl_down_sync(0xffffffffu, v, o);
        if (lane == 0) wcnt[wp] = v;
    }
    __syncthreads();
    if (t < 24) {
        float s = wsum[0][t] + wsum[1][t] + wsum[2][t] + wsum[3][t];
        float ct = wcnt[0] + wcnt[1] + wcnt[2] + wcnt[3];
        int idx = (bh * MCNT + m) * HDIM + t;
        g_agg[idx] = (s + g_vc[idx]) / (ct + 1.f);
    }
}

// ---------------- K4: dispatch back to tokens (round-1 exact) ----------------
__global__ void k_dispatch() {
    int bh = blockIdx.x;
    int b = bh >> 2, e = bh & 3;
    __shared__ float agg[16][24];
    int t = threadIdx.x;
    for (int i = t; i < 384; i += 192) agg[i / 24][i % 24] = g_agg[bh * 384 + i];
    __syncthreads();
    int c = t % 24, tl = t / 24;
    for (int n0 = 0; n0 < N_TOK; n0 += 8) {
        int n = n0 + tl;
        float s = g_s[(size_t)bh * N_TOK + n];
        int mm = g_m[(size_t)bh * N_TOK + n];
        g_merged[((size_t)b * N_TOK + n) * CH + e * HDIM + c] = s * agg[mm][c];
    }
}

// ---------------- launch (round-1 exact) ----------------
extern "C" void kernel_launch(void* const* d_in, const int* in_sizes, int n_in,
                              void* d_out, int out_size) {
    const float* x       = (const float*)d_in[0];
    const float* f_w     = (const float*)d_in[1];
    const float* f_b     = (const float*)d_in[2];
    const float* v_w     = (const float*)d_in[3];
    const float* v_b     = (const float*)d_in[4];
    const float* proj_w  = (const float*)d_in[5];
    const float* proj_b  = (const float*)d_in[6];
    const float* sim_a   = (const float*)d_in[7];
    const float* sim_b   = (const float*)d_in[8];
    float* out = (float*)d_out;

    k_concat<<<(CH2 * DIMC + CH2 + 255) / 256, 256>>>(f_w, f_b, v_w, v_b);
    k_gemm_fv<<<dim3(MTOT / 128, CH2 / 64), 128>>>(x);
    k_pool<<<dim3(BH, MCNT), 192>>>();
    k_assign<<<BH, 256>>>(sim_a, sim_b);
    k_agg<<<dim3(BH, MCNT), 128>>>();
    k_dispatch<<<BH, 192>>>();
    k_gemm_proj<<<dim3(MTOT / 128, OUTC / 64), 128>>>(proj_w, proj_b, out);
}

// round 13
// speedup vs baseline: 1.2171x; 1.2171x over previous
#include <cuda_runtime.h>
#include <cstdint>

// ---------------- problem constants ----------------
#define BB      64          // batch
#define PP      56          // grid side
#define N_TOK   3136        // P*P
#define DIMC    256         // input channels
#define HEADS   4
#define HDIM    24
#define CH      96          // HEADS*HDIM
#define CH2     192         // feat+val
#define MCNT    16          // cluster centers
#define BH      256         // B*HEADS
#define OUTC    256
#define MTOT    (BB * N_TOK)   // 200704 rows

// ---------------- scratch ----------------
__device__ float g_w12[CH2 * DIMC];
__device__ float g_b12[CH2];
__device__ float g_fv[(size_t)MTOT * CH2];
__device__ float g_cn[BH * MCNT * HDIM];
__device__ float g_vc[BH * MCNT * HDIM];
__device__ float g_agg[BH * MCNT * HDIM];
__device__ float g_s[(size_t)BH * N_TOK];
__device__ unsigned char g_m[(size_t)BH * N_TOK];
__device__ float g_ap[BH * MCNT * OUTC];       // agg @ proj slice [4096,256]

// ---------------- K0: concat weights/biases (round-9 exact) ----------------
__global__ void k_concat(const float* __restrict__ fw, const float* __restrict__ fb,
                         const float* __restrict__ vw, const float* __restrict__ vb) {
    int i = blockIdx.x * blockDim.x + threadIdx.x;
    if (i < CH * DIMC)                 g_w12[i] = fw[i];
    else if (i < CH2 * DIMC)           g_w12[i] = vw[i - CH * DIMC];
    else if (i < CH2 * DIMC + CH)      g_b12[i - CH2 * DIMC] = fb[i - CH2 * DIMC];
    else if (i < CH2 * DIMC + CH2)     g_b12[i - CH2 * DIMC] = vb[i - CH2 * DIMC - CH];
}

// ---------------- packed f32x2 helpers (round-9 exact) ----------------
__device__ __forceinline__ unsigned long long bcast2(float x) {
    unsigned long long r;
    asm("mov.b64 %0, {%1, %1};" : "=l"(r) : "r"(__float_as_uint(x)));
    return r;
}
#define FMA2(acc, a2, b2) \
    asm("fma.rn.f32x2 %0, %1, %2, %0;" : "+l"(acc) : "l"(a2), "l"(b2))

// ---------------- fv GEMM (round-9 exact, passed with delta=0) ----------------
template <int K, int NC>
__device__ __forceinline__ void gemm_body(const float* __restrict__ A,
                                          const float* __restrict__ W,
                                          const float* __restrict__ bias,
                                          float* __restrict__ C) {
    __shared__ float As[8][128];
    __shared__ float Bs[8][64];
    const int tid = threadIdx.x;
    const int m0 = blockIdx.x * 128;
    const int n0 = blockIdx.y * 64;
    const int ty = tid >> 3;
    const int tx = tid & 7;

    const float* Ap = A + (size_t)(m0 + tid) * K;
    const int br = tid >> 1;
    const int bk = (tid & 1) * 4;
    const float* Wp = W + (size_t)(n0 + br) * K + bk;

    float4 a0 = *(const float4*)(Ap);
    float4 a1 = *(const float4*)(Ap + 4);
    float4 b0 = *(const float4*)(Wp);

    unsigned long long acc2[8][4];
    const unsigned long long zz = 0ull;
#pragma unroll
    for (int i = 0; i < 8; i++)
#pragma unroll
        for (int j = 0; j < 4; j++) acc2[i][j] = zz;

    const int KT = K / 8;
    for (int kt = 0; kt < KT; ++kt) {
        As[0][tid] = a0.x; As[1][tid] = a0.y; As[2][tid] = a0.z; As[3][tid] = a0.w;
        As[4][tid] = a1.x; As[5][tid] = a1.y; As[6][tid] = a1.z; As[7][tid] = a1.w;
        Bs[bk + 0][br] = b0.x; Bs[bk + 1][br] = b0.y; Bs[bk + 2][br] = b0.z; Bs[bk + 3][br] = b0.w;
        __syncthreads();
        if (kt + 1 < KT) {
            a0 = *(const float4*)(Ap + (kt + 1) * 8);
            a1 = *(const float4*)(Ap + (kt + 1) * 8 + 4);
            b0 = *(const float4*)(Wp + (kt + 1) * 8);
        }
#pragma unroll
        for (int k = 0; k < 8; k++) {
            float ra[8];
            *(float4*)(ra)     = *(const float4*)&As[k][ty * 8];
            *(float4*)(ra + 4) = *(const float4*)&As[k][ty * 8 + 4];
            unsigned long long rb2[4];
            {
                const ulonglong2 u0 = *(const ulonglong2*)&Bs[k][tx * 8];
                const ulonglong2 u1 = *(const ulonglong2*)&Bs[k][tx * 8 + 4];
                rb2[0] = u0.x; rb2[1] = u0.y; rb2[2] = u1.x; rb2[3] = u1.y;
            }
#pragma unroll
            for (int i = 0; i < 8; i++) {
                const unsigned long long a2 = bcast2(ra[i]);
                FMA2(acc2[i][0], a2, rb2[0]);
                FMA2(acc2[i][1], a2, rb2[1]);
                FMA2(acc2[i][2], a2, rb2[2]);
                FMA2(acc2[i][3], a2, rb2[3]);
            }
        }
        __syncthreads();
    }

    float bb[8];
#pragma unroll
    for (int j = 0; j < 8; j++) bb[j] = bias[n0 + tx * 8 + j];
#pragma unroll
    for (int i = 0; i < 8; i++) {
        float* Cp = C + (size_t)(m0 + ty * 8 + i) * NC + n0 + tx * 8;
        float4 o0, o1;
        o0.x = __uint_as_float((unsigned)(acc2[i][0]))       + bb[0];
        o0.y = __uint_as_float((unsigned)(acc2[i][0] >> 32)) + bb[1];
        o0.z = __uint_as_float((unsigned)(acc2[i][1]))       + bb[2];
        o0.w = __uint_as_float((unsigned)(acc2[i][1] >> 32)) + bb[3];
        o1.x = __uint_as_float((unsigned)(acc2[i][2]))       + bb[4];
        o1.y = __uint_as_float((unsigned)(acc2[i][2] >> 32)) + bb[5];
        o1.z = __uint_as_float((unsigned)(acc2[i][3]))       + bb[6];
        o1.w = __uint_as_float((unsigned)(acc2[i][3] >> 32)) + bb[7];
        *(float4*)(Cp) = o0;
        *(float4*)(Cp + 4) = o1;
    }
}

__global__ void k_gemm_fv(const float* __restrict__ x) {
    gemm_body<DIMC, CH2>(x, g_w12, g_b12, g_fv);
}

// ---------------- K2: pooling + center l2-norm (round-9 exact) ----------------
__global__ void k_pool() {
    int bh = blockIdx.x, m = blockIdx.y;
    int b = bh >> 2, e = bh & 3;
    int t = threadIdx.x;
    int c = t % 48, sub = t / 48;
    int w0 = (m >> 2) * 14, h0 = (m & 3) * 14;
    int off = (c < 24) ? (e * HDIM + c) : (CH + e * HDIM + (c - 24));
    float acc = 0.f;
    for (int ti = sub; ti < 196; ti += 4) {
        int n = (w0 + ti / 14) * PP + h0 + ti % 14;
        acc += g_fv[((size_t)b * N_TOK + n) * CH2 + off];
    }
    __shared__ float red[4][48];
    __shared__ float meanv[48];
    __shared__ float sinv;
    red[sub][c] = acc;
    __syncthreads();
    if (t < 48) meanv[t] = (red[0][t] + red[1][t] + red[2][t] + red[3][t]) * (1.f / 196.f);
    __syncthreads();
    if (t == 0) {
        float s = 0.f;
        for (int i = 0; i < 24; i++) s += meanv[i] * meanv[i];
        sinv = 1.f / fmaxf(sqrtf(s), 1e-12f);
    }
    __syncthreads();
    if (t < 24)      g_cn[(bh * MCNT + m) * HDIM + t] = meanv[t] * sinv;
    else if (t < 48) g_vc[(bh * MCNT + m) * HDIM + (t - 24)] = meanv[t];
}

// ---------------- K3a: cosine-sim + leaky + top-1 (round-9 exact) ----------------
__global__ void k_assign(const float* __restrict__ alpha_p, const float* __restrict__ beta_p) {
    int bh = blockIdx.x;
    int b = bh >> 2, e = bh & 3;
    __shared__ float cnT[24][16];
    int t = threadIdx.x;
    for (int i = t; i < 384; i += 256) {
        int m = i / 24, c = i % 24;
        cnT[c][m] = g_cn[(bh * MCNT + m) * HDIM + c];
    }
    __syncthreads();
    float alpha = alpha_p[0], beta = beta_p[0];
    for (int n = t; n < N_TOK; n += 256) {
        const float* fp = g_fv + ((size_t)b * N_TOK + n) * CH2 + e * HDIM;
        float f[24];
#pragma unroll
        for (int i = 0; i < 6; i++) *(float4*)(f + 4 * i) = *(const float4*)(fp + 4 * i);
        float ss = 0.f;
#pragma unroll
        for (int c = 0; c < 24; c++) ss += f[c] * f[c];
        float inv = 1.f / fmaxf(sqrtf(ss), 1e-12f);
        float dm[16];
#pragma unroll
        for (int m = 0; m < 16; m++) dm[m] = 0.f;
#pragma unroll
        for (int c = 0; c < 24; c++) {
            float fc = f[c];
#pragma unroll
            for (int m = 0; m < 16; m++) dm[m] += cnT[c][m] * fc;
        }
        float best = -1e30f; int bm = 0;
#pragma unroll
        for (int m = 0; m < 16; m++) {
            float v = beta + alpha * (dm[m] * inv);
            v = (v > 0.f) ? v : 0.2f * v;
            if (v > best) { best = v; bm = m; }
        }
        g_s[(size_t)bh * N_TOK + n] = best;
        g_m[(size_t)bh * N_TOK + n] = (unsigned char)bm;
    }
}

// ---------------- K3b: masked aggregation (round-9 exact) ----------------
__global__ void k_agg() {
    int bh = blockIdx.x, m = blockIdx.y;
    int b = bh >> 2, e = bh & 3;
    int t = threadIdx.x;
    float acc[24];
#pragma unroll
    for (int c = 0; c < 24; c++) acc[c] = 0.f;
    float cnt = 0.f;
    for (int n = t; n < N_TOK; n += 128) {
        if (g_m[(size_t)bh * N_TOK + n] == (unsigned char)m) {
            float s = g_s[(size_t)bh * N_TOK + n];
            const float* vp = g_fv + ((size_t)b * N_TOK + n) * CH2 + CH + e * HDIM;
            float vv[24];
#pragma unroll
            for (int i = 0; i < 6; i++) *(float4*)(vv + 4 * i) = *(const float4*)(vp + 4 * i);
#pragma unroll
            for (int c = 0; c < 24; c++) acc[c] += s * vv[c];
            cnt += 1.f;
        }
    }
    __shared__ float wsum[4][24];
    __shared__ float wcnt[4];
    int lane = t & 31, wp = t >> 5;
#pragma unroll
    for (int c = 0; c < 24; c++) {
        float v = acc[c];
        for (int o = 16; o; o >>= 1) v += __shfl_down_sync(0xffffffffu, v, o);
        if (lane == 0) wsum[wp][c] = v;
    }
    {
        float v = cnt;
        for (int o = 16; o; o >>= 1) v += __shfl_down_sync(0xffffffffu, v, o);
        if (lane == 0) wcnt[wp] = v;
    }
    __syncthreads();
    if (t < 24) {
        float s = wsum[0][t] + wsum[1][t] + wsum[2][t] + wsum[3][t];
        float ct = wcnt[0] + wcnt[1] + wcnt[2] + wcnt[3];
        int idx = (bh * MCNT + m) * HDIM + t;
        g_agg[idx] = (s + g_vc[idx]) / (ct + 1.f);
    }
}

// ---------------- K4 NEW: fold agg through proj slice -> g_ap ----------------
// g_ap[bh,m,o] = sum_j agg[bh,m,j] * proj_w[o, e*24+j]   (j ascending = ref k-order)
__global__ void k_ap(const float* __restrict__ proj_w) {
    int bh = blockIdx.x, m = blockIdx.y;
    int e = bh & 3;
    int t = threadIdx.x;              // t = output channel o (256)
    __shared__ float sm_agg[24];
    if (t < 24) sm_agg[t] = g_agg[(bh * MCNT + m) * HDIM + t];
    __syncthreads();
    const float* pw = proj_w + (size_t)t * CH + e * HDIM;
    float ap = 0.f;
#pragma unroll
    for (int j = 0; j < 24; j++) ap += sm_agg[j] * pw[j];
    g_ap[(bh * MCNT + m) * OUTC + t] = ap;
}

// ---------------- K5 NEW: output gather  out[b,n,o] = pb[o] + sum_e s*ap ----------------
__global__ void k_out(const float* __restrict__ proj_b, float* __restrict__ out) {
    int b = blockIdx.x;
    int n0 = blockIdx.y * 32;
    int t = threadIdx.x;              // t = output channel o
    float pb = proj_b[t];
    for (int dn = 0; dn < 32; dn++) {
        int n = n0 + dn;
        float acc = pb;
#pragma unroll
        for (int e = 0; e < 4; e++) {
            int bh = b * 4 + e;
            int mm = g_m[(size_t)bh * N_TOK + n];
            float s = g_s[(size_t)bh * N_TOK + n];
            acc += s * g_ap[(bh * MCNT + mm) * OUTC + t];
        }
        out[((size_t)b * N_TOK + n) * OUTC + t] = acc;
    }
}

// ---------------- launch ----------------
extern "C" void kernel_launch(void* const* d_in, const int* in_sizes, int n_in,
                              void* d_out, int out_size) {
    const float* x       = (const float*)d_in[0];
    const float* f_w     = (const float*)d_in[1];
    const float* f_b     = (const float*)d_in[2];
    const float* v_w     = (const float*)d_in[3];
    const float* v_b     = (const float*)d_in[4];
    const float* proj_w  = (const float*)d_in[5];
    const float* proj_b  = (const float*)d_in[6];
    const float* sim_a   = (const float*)d_in[7];
    const float* sim_b   = (const float*)d_in[8];
    float* out = (float*)d_out;

    k_concat<<<(CH2 * DIMC + CH2 + 255) / 256, 256>>>(f_w, f_b, v_w, v_b);
    k_gemm_fv<<<dim3(MTOT / 128, CH2 / 64), 128>>>(x);
    k_pool<<<dim3(BH, MCNT), 192>>>();
    k_assign<<<BH, 256>>>(sim_a, sim_b);
    k_agg<<<dim3(BH, MCNT), 128>>>();
    k_ap<<<dim3(BH, MCNT), 256>>>(proj_w);
    k_out<<<dim3(BB, N_TOK / 32), 256>>>(proj_b, out);
}